// round 15
// baseline (speedup 1.0000x reference)
#include <cuda_runtime.h>
#include <cuda_fp16.h>
#include <cstdint>

#define S_LEN   4096
#define HID_    2880
#define H_KV_   8
#define G_      8
#define W_      128
#define NB_     32
#define QKV_OUT 5120
#define ATTN_W  4096
#define HALF_   32

// ---------------------------------------------------------------------------
// Scratch
// ---------------------------------------------------------------------------
__device__ __half g_qkv_h [(size_t)S_LEN * QKV_OUT];   // fp16 qkv (post-rope, q pre-scaled)
__device__ __half g_hs_h  [(size_t)S_LEN * HID_];
__device__ __half g_wqkv_h[(size_t)HID_ * QKV_OUT];    // fp16 Wqkv, ROW-major [K,N]
__device__ __half g_wo_h  [(size_t)ATTN_W * HID_];     // fp16 Wo,   ROW-major [K,N]
__device__ __half g_attn_h[(size_t)S_LEN * ATTN_W];

// ---------------------------------------------------------------------------
// PTX helpers (plain sm_100 ISA)
// ---------------------------------------------------------------------------
__device__ __forceinline__ uint32_t smem_u32(const void* p) {
    uint32_t a;
    asm("{ .reg .u64 t; cvta.to.shared.u64 t, %1; cvt.u32.u64 %0, t; }" : "=r"(a) : "l"(p));
    return a;
}
__device__ __forceinline__ void cpasync16(uint32_t dst, const void* src, uint32_t sz) {
    asm volatile("cp.async.cg.shared.global [%0], [%1], 16, %2;\n"
                 :: "r"(dst), "l"(src), "r"(sz) : "memory");
}
#define CP_COMMIT() asm volatile("cp.async.commit_group;" ::: "memory")
#define CP_WAIT1()  asm volatile("cp.async.wait_group 1;" ::: "memory")

#define LDSM_X4(d0, d1, d2, d3, a)                                             \
    asm volatile("ldmatrix.sync.aligned.m8n8.x4.shared.b16 {%0,%1,%2,%3}, [%4];"\
        : "=r"(d0), "=r"(d1), "=r"(d2), "=r"(d3) : "r"(a))

#define LDSM_X4_T(d0, d1, d2, d3, a)                                           \
    asm volatile("ldmatrix.sync.aligned.m8n8.x4.trans.shared.b16 {%0,%1,%2,%3}, [%4];"\
        : "=r"(d0), "=r"(d1), "=r"(d2), "=r"(d3) : "r"(a))

#define MMA_F16(d, a, b)                                                       \
    asm volatile("mma.sync.aligned.m16n8k16.row.col.f32.f16.f16.f32 "          \
        "{%0,%1,%2,%3}, {%4,%5,%6,%7}, {%8,%9}, {%0,%1,%2,%3};"                \
        : "+f"((d)[0]), "+f"((d)[1]), "+f"((d)[2]), "+f"((d)[3])               \
        : "r"((a)[0]), "r"((a)[1]), "r"((a)[2]), "r"((a)[3]),                  \
          "r"((b)[0]), "r"((b)[1]))

__device__ __forceinline__ uint32_t pack_h2(float x, float y) {
    __half2 h = __floats2half2_rn(x, y);
    return *reinterpret_cast<uint32_t*>(&h);
}
__device__ __forceinline__ uint32_t pack_f16x2(float lo, float hi) {
    uint32_t r;
    asm("cvt.rn.f16x2.f32 %0, %1, %2;" : "=r"(r) : "f"(hi), "f"(lo));
    return r;
}
__device__ __forceinline__ uint32_t ex2_h2(uint32_t x) {
    uint32_t r;
    asm("ex2.approx.f16x2 %0, %1;" : "=r"(r) : "r"(x));
    return r;
}

// ---------------------------------------------------------------------------
// fp16 GEMM:  C[M,Nn] = A[M,K] @ B[K,Nn] + bias   (B ROW-major — no transpose
// prep; B fragments via ldmatrix.x4.trans, exactly the validated V path).
// CTA 128x128, 4 warps, warp tile 64x64, K-step 64, 3-stage pipeline,
// double-buffered register fragments.
// B stage tile: 64 k-rows x 128 n-cols as two 8KB n-half blocks,
// 128B rows, swizzle chunk' = chunk ^ (row & 7).
// ---------------------------------------------------------------------------
#define GSTAGES     3
#define STAGE_BYTES 32768     // A 16KB + B 16KB
#define GM_SMEM     (GSTAGES * STAGE_BYTES)

template <bool ROPE>
__global__ void __launch_bounds__(128, 2)
gemm_h(const __half* __restrict__ A, const __half* __restrict__ B,
       const float* __restrict__ bias, void* __restrict__ Cv,
       const float* __restrict__ cosb, const float* __restrict__ sinb,
       int Nn, int K)
{
    extern __shared__ char smem[];
    const uint32_t sb = smem_u32(smem);
    const int tid  = threadIdx.x;
    const int wid  = tid >> 5;
    const int lane = tid & 31;
    const int m0   = blockIdx.y << 7;
    const int n0   = blockIdx.x << 7;
    const int wm   = (wid & 1) << 6;    // warp M offset: 0,64
    const int wn   = (wid >> 1) << 6;   // warp N offset: 0,64

    float acc[4][8][4];
#pragma unroll
    for (int a = 0; a < 4; a++)
#pragma unroll
        for (int b = 0; b < 8; b++)
#pragma unroll
            for (int c = 0; c < 4; c++) acc[a][b][c] = 0.f;

    const int nkt = K >> 6;

    auto load_stage = [&](int kt, int slot) {
        const uint32_t abase = sb + slot * STAGE_BYTES;
        const uint32_t bbase = abase + 16384;
        const int k0 = kt << 6;
        // A: 128 m-rows x 8 chunks (128B rows, swizzled)
#pragma unroll
        for (int j = 0; j < 8; j++) {
            const int f = tid + (j << 7);
            const int r = f >> 3, c = f & 7;
            const uint32_t off = (uint32_t)(r << 7) + ((c ^ (r & 7)) << 4);
            cpasync16(abase + off, A + (size_t)(m0 + r) * K + k0 + (c << 3), 16u);
        }
        // B: 64 k-rows x 16 chunks (two 8KB n-half blocks)
#pragma unroll
        for (int j = 0; j < 8; j++) {
            const int f = tid + (j << 7);
            const int r = f >> 4;            // k-row 0..63
            const int c = f & 15;            // 16B chunk 0..15 (n dim)
            const int h = c >> 3;            // n-half block
            const int c7 = c & 7;
            const uint32_t off = (uint32_t)(h << 13) + (uint32_t)(r << 7)
                                 + ((c7 ^ (r & 7)) << 4);
            const int col = n0 + (c << 3);
            const int scol = (col < Nn) ? col : 0;
            cpasync16(bbase + off, B + (size_t)(k0 + r) * Nn + scol,
                      (col < Nn) ? 16u : 0u);
        }
    };

    for (int s = 0; s < 2; s++) {
        if (s < nkt) load_stage(s, s);
        CP_COMMIT();
    }

    for (int t = 0; t < nkt; t++) {
        CP_WAIT1();
        __syncthreads();
        if (t + 2 < nkt) load_stage(t + 2, (t + 2) % 3);
        CP_COMMIT();

        const uint32_t abase = sb + (t % 3) * STAGE_BYTES;
        const uint32_t bbase = abase + 16384 + ((uint32_t)(wn >> 6) << 13);

        auto ldfrags = [&](int kh, uint32_t (&af_b)[4][4], uint32_t (&bf_b)[8][2]) {
#pragma unroll
            for (int mt = 0; mt < 4; mt++) {
                const int r = wm + (mt << 4) + (lane & 15);
                const int c = (kh << 1) + (lane >> 4);
                const uint32_t addr =
                    abase + (uint32_t)(r << 7) + ((c ^ (r & 7)) << 4);
                LDSM_X4(af_b[mt][0], af_b[mt][1], af_b[mt][2], af_b[mt][3], addr);
            }
            // B: trans fragments from row-major [k][n] tile (V-path mapping)
#pragma unroll
            for (int nq = 0; nq < 4; nq++) {
                const int row = (kh << 4) + (lane & 15);     // k index
                const int cc  = (nq << 1) + (lane >> 4);     // n 16B chunk
                const uint32_t addr =
                    bbase + (uint32_t)(row << 7) + ((cc ^ (row & 7)) << 4);
                uint32_t t0, t1, t2, t3;
                LDSM_X4_T(t0, t1, t2, t3, addr);
                bf_b[nq * 2][0] = t0;     bf_b[nq * 2][1] = t1;
                bf_b[nq * 2 + 1][0] = t2; bf_b[nq * 2 + 1][1] = t3;
            }
        };

        uint32_t af[2][4][4];
        uint32_t bf[2][8][2];
        ldfrags(0, af[0], bf[0]);

#pragma unroll
        for (int kh = 0; kh < 4; kh++) {
            const int cur = kh & 1;
            if (kh < 3) ldfrags(kh + 1, af[cur ^ 1], bf[cur ^ 1]);
#pragma unroll
            for (int mt = 0; mt < 4; mt++)
#pragma unroll
                for (int nt = 0; nt < 8; nt++)
                    MMA_F16(acc[mt][nt], af[cur][mt], bf[cur][nt]);
        }
    }

    // ---- epilogue ----
    const int r_l = lane >> 2;
    const int c_l = (lane & 3) << 1;

#pragma unroll
    for (int mt = 0; mt < 4; mt++)
#pragma unroll
        for (int nt = 0; nt < 8; nt++) {
            const int col = n0 + wn + (nt << 3) + c_l;
            if (col < Nn) {
                const float2 bz = *reinterpret_cast<const float2*>(bias + col);
                acc[mt][nt][0] += bz.x; acc[mt][nt][1] += bz.y;
                acc[mt][nt][2] += bz.x; acc[mt][nt][3] += bz.y;
            }
        }

    if (ROPE) {
        const int hidx = (n0 + wn) >> 6;       // head index (warp N-tile head-aligned)
        if (hidx < 72) {                        // q + k heads get rope
#pragma unroll
            for (int mt = 0; mt < 4; mt++) {
                const int r0 = m0 + wm + (mt << 4) + r_l;
#pragma unroll
                for (int nt = 0; nt < 4; nt++) {
                    const int d = (nt << 3) + c_l;          // 0..30 (pair with d+32)
                    const float2 c0 = *reinterpret_cast<const float2*>(cosb + (size_t)r0 * 32 + d);
                    const float2 s0 = *reinterpret_cast<const float2*>(sinb + (size_t)r0 * 32 + d);
                    const float2 c1 = *reinterpret_cast<const float2*>(cosb + (size_t)(r0 + 8) * 32 + d);
                    const float2 s1 = *reinterpret_cast<const float2*>(sinb + (size_t)(r0 + 8) * 32 + d);
                    float x1, x2;
                    x1 = acc[mt][nt][0]; x2 = acc[mt][nt + 4][0];
                    acc[mt][nt][0]     = x1 * c0.x - x2 * s0.x;
                    acc[mt][nt + 4][0] = x2 * c0.x + x1 * s0.x;
                    x1 = acc[mt][nt][1]; x2 = acc[mt][nt + 4][1];
                    acc[mt][nt][1]     = x1 * c0.y - x2 * s0.y;
                    acc[mt][nt + 4][1] = x2 * c0.y + x1 * s0.y;
                    x1 = acc[mt][nt][2]; x2 = acc[mt][nt + 4][2];
                    acc[mt][nt][2]     = x1 * c1.x - x2 * s1.x;
                    acc[mt][nt + 4][2] = x2 * c1.x + x1 * s1.x;
                    x1 = acc[mt][nt][3]; x2 = acc[mt][nt + 4][3];
                    acc[mt][nt][3]     = x1 * c1.y - x2 * s1.y;
                    acc[mt][nt + 4][3] = x2 * c1.y + x1 * s1.y;
                }
            }
        }
        if (hidx < 64) {                        // fold 1/sqrt(d) into q
#pragma unroll
            for (int mt = 0; mt < 4; mt++)
#pragma unroll
                for (int nt = 0; nt < 8; nt++) {
                    acc[mt][nt][0] *= 0.125f; acc[mt][nt][1] *= 0.125f;
                    acc[mt][nt][2] *= 0.125f; acc[mt][nt][3] *= 0.125f;
                }
        }
        __half* Ch = (__half*)Cv;
#pragma unroll
        for (int mt = 0; mt < 4; mt++) {
            const int row = m0 + wm + (mt << 4) + r_l;
#pragma unroll
            for (int nt = 0; nt < 8; nt++) {
                const int col = n0 + wn + (nt << 3) + c_l;
                *reinterpret_cast<uint32_t*>(Ch + (size_t)row * Nn + col) =
                    pack_h2(acc[mt][nt][0], acc[mt][nt][1]);
                *reinterpret_cast<uint32_t*>(Ch + (size_t)(row + 8) * Nn + col) =
                    pack_h2(acc[mt][nt][2], acc[mt][nt][3]);
            }
        }
    } else {
        float* C = (float*)Cv;
#pragma unroll
        for (int mt = 0; mt < 4; mt++) {
            const int row = m0 + wm + (mt << 4) + r_l;
#pragma unroll
            for (int nt = 0; nt < 8; nt++) {
                const int col = n0 + wn + (nt << 3) + c_l;
                if (col < Nn) {
                    float2 o0, o1;
                    o0.x = acc[mt][nt][0]; o0.y = acc[mt][nt][1];
                    o1.x = acc[mt][nt][2]; o1.y = acc[mt][nt][3];
                    *reinterpret_cast<float2*>(C + (size_t)row * Nn + col)       = o0;
                    *reinterpret_cast<float2*>(C + (size_t)(row + 8) * Nn + col) = o1;
                }
            }
        }
    }
}

// ---------------------------------------------------------------------------
// Prep: pure streaming f2h of hidden + Wqkv + Wo (NO transposes — the GEMM
// consumes row-major B via ldmatrix.trans).
// ---------------------------------------------------------------------------
#define PREP_HS_BLOCKS 11520             // 4096*2880/4/256
#define PREP_W1_BLOCKS 14400             // 2880*5120/4/256
#define PREP_W2_BLOCKS 11520             // 4096*2880/4/256
#define PREP_BLOCKS    (PREP_HS_BLOCKS + PREP_W1_BLOCKS + PREP_W2_BLOCKS)

__global__ void __launch_bounds__(256)
prep_kernel(const float* __restrict__ hs,   __half* __restrict__ hsh,
            const float* __restrict__ Wqkv, __half* __restrict__ wqkvh,
            const float* __restrict__ Wo,   __half* __restrict__ woh)
{
    const int bid = blockIdx.x;
    const float* src;
    __half* dst;
    int i;
    if (bid < PREP_HS_BLOCKS) {
        src = hs;  dst = hsh;  i = bid * 256 + threadIdx.x;
    } else if (bid < PREP_HS_BLOCKS + PREP_W1_BLOCKS) {
        src = Wqkv; dst = wqkvh; i = (bid - PREP_HS_BLOCKS) * 256 + threadIdx.x;
    } else {
        src = Wo;  dst = woh; i = (bid - PREP_HS_BLOCKS - PREP_W1_BLOCKS) * 256 + threadIdx.x;
    }
    const float4 v = reinterpret_cast<const float4*>(src)[i];
    __half2* d = reinterpret_cast<__half2*>(dst) + 2 * i;
    d[0] = __floats2half2_rn(v.x, v.y);
    d[1] = __floats2half2_rn(v.z, v.w);
}

// ---------------------------------------------------------------------------
// Tensor-core sliding-window flash attention with sinks (R14 version:
// fp16x2 ex2 softmax, denominators via P @ ones MMA).
// ---------------------------------------------------------------------------
#define AT_SMEM 81920   // K 32KB | V 32KB | Q 16KB

__global__ void __launch_bounds__(256, 1)
attn_tc(const __half* __restrict__ qkv, const float* __restrict__ sinks,
        __half* __restrict__ out)
{
    extern __shared__ __align__(16) char asmem[];
    char* Kc = asmem;
    char* Vc = asmem + 32768;
    char* Qc = asmem + 65536;
    const uint32_t kb = smem_u32(Kc);
    const uint32_t vb = smem_u32(Vc);
    const uint32_t qb = smem_u32(Qc);

    const int b    = blockIdx.x;
    const int kv   = blockIdx.y;
    const int tid  = threadIdx.x;
    const int wid  = tid >> 5;
    const int lane = tid & 31;

    for (int i = tid; i < 2048; i += 256) {
        const int tk = i >> 3, c = i & 7;
        uint4 kk = make_uint4(0u, 0u, 0u, 0u), vv = kk;
        if (tk >= 128 || b > 0) {
            const int token = (tk < 128) ? ((b - 1) * W_ + tk) : (b * W_ + tk - 128);
            const __half* kp = qkv + (size_t)token * QKV_OUT + 4096 + kv * 64 + c * 8;
            kk = *reinterpret_cast<const uint4*>(kp);
            vv = *reinterpret_cast<const uint4*>(kp + 512);
        }
        const uint32_t off = (uint32_t)(tk << 7) + ((c ^ (tk & 7)) << 4);
        *reinterpret_cast<uint4*>(Kc + off) = kk;
        *reinterpret_cast<uint4*>(Vc + off) = vv;
    }

    const int q0    = wid << 4;
    const int r_lo  = lane >> 2;
    const int cpair = (lane & 3) << 1;
    const uint32_t ONES2 = 0x3C003C00u;
    const uint32_t ones_frag[2] = { ONES2, ONES2 };
    const float L2E = 1.4426950408889634f;

    for (int g = 0; g < G_; g++) {
        __syncthreads();
        for (int i = tid; i < 1024; i += 256) {
            const int r = i >> 3, c = i & 7;
            const __half* qp = qkv + (size_t)(b * W_ + r) * QKV_OUT
                               + (kv * G_ + g) * 64 + c * 8;
            *reinterpret_cast<uint4*>(Qc + (r << 7) + ((c ^ (r & 7)) << 4)) =
                *reinterpret_cast<const uint4*>(qp);
        }
        __syncthreads();

        uint32_t aq[4][4];
#pragma unroll
        for (int kt = 0; kt < 4; kt++) {
            const int row = q0 + (lane & 15);
            const int ch  = (kt << 1) + (lane >> 4);
            const uint32_t addr = qb + (uint32_t)(row << 7) + ((ch ^ (row & 7)) << 4);
            LDSM_X4(aq[kt][0], aq[kt][1], aq[kt][2], aq[kt][3], addr);
        }

        const float sink = sinks[kv * G_ + g];
        float m0 = sink, m1 = sink;
        float dn0 = 1.f, dn1 = 1.f;
        float o[8][4];
#pragma unroll
        for (int j = 0; j < 8; j++)
#pragma unroll
            for (int c = 0; c < 4; c++) o[j][c] = 0.f;

#pragma unroll
        for (int ch2 = 0; ch2 < 2; ch2++) {
            if (b == 0 && ch2 == 0) continue;

            float s[16][4];
#pragma unroll
            for (int nt = 0; nt < 16; nt++)
#pragma unroll
                for (int c = 0; c < 4; c++) s[nt][c] = 0.f;

#pragma unroll
            for (int nt2 = 0; nt2 < 8; nt2++) {
#pragma unroll
                for (int kt = 0; kt < 4; kt++) {
                    const int row = (ch2 << 7) + (nt2 << 4)
                                    + ((lane >> 4) << 3) + (lane & 7);
                    const int cc  = (kt << 1) + ((lane >> 3) & 1);
                    const uint32_t addr =
                        kb + (uint32_t)(row << 7) + ((cc ^ (row & 7)) << 4);
                    uint32_t t0, t1, t2, t3;
                    LDSM_X4(t0, t1, t2, t3, addr);
                    uint32_t bf0[2] = {t0, t1}, bf1[2] = {t2, t3};
                    MMA_F16(s[nt2 * 2],     aq[kt], bf0);
                    MMA_F16(s[nt2 * 2 + 1], aq[kt], bf1);
                }
            }

            const int qi_lo = q0 + r_lo;
            const int qi_hi = qi_lo + 8;
#pragma unroll
            for (int nt = 0; nt < 16; nt++) {
                const int ki = (ch2 << 7) + (nt << 3) + cpair;
                const int d0i = ki - qi_lo, d1i = ki + 1 - qi_lo;
                const int d2i = ki - qi_hi, d3i = ki + 1 - qi_hi;
                if (d0i < 1 || d0i > 128) s[nt][0] = -1e30f;
                if (d1i < 1 || d1i > 128) s[nt][1] = -1e30f;
                if (d2i < 1 || d2i > 128) s[nt][2] = -1e30f;
                if (d3i < 1 || d3i > 128) s[nt][3] = -1e30f;
            }

            float mx0 = -1e30f, mx1 = -1e30f;
#pragma unroll
            for (int nt = 0; nt < 16; nt++) {
                mx0 = fmaxf(mx0, fmaxf(s[nt][0], s[nt][1]));
                mx1 = fmaxf(mx1, fmaxf(s[nt][2], s[nt][3]));
            }
            mx0 = fmaxf(mx0, __shfl_xor_sync(0xffffffffu, mx0, 1));
            mx0 = fmaxf(mx0, __shfl_xor_sync(0xffffffffu, mx0, 2));
            mx1 = fmaxf(mx1, __shfl_xor_sync(0xffffffffu, mx1, 1));
            mx1 = fmaxf(mx1, __shfl_xor_sync(0xffffffffu, mx1, 2));
            const float nm0 = fmaxf(m0, mx0), nm1 = fmaxf(m1, mx1);
            const float f0 = __expf(m0 - nm0), f1 = __expf(m1 - nm1);

            const float c0a = -nm0 * L2E;
            const float c1a = -nm1 * L2E;
            uint32_t p[16][2];
#pragma unroll
            for (int nt = 0; nt < 16; nt++) {
                const float t0 = fmaf(s[nt][0], L2E, c0a);
                const float t1 = fmaf(s[nt][1], L2E, c0a);
                const float t2 = fmaf(s[nt][2], L2E, c1a);
                const float t3 = fmaf(s[nt][3], L2E, c1a);
                p[nt][0] = ex2_h2(pack_f16x2(t0, t1));
                p[nt][1] = ex2_h2(pack_f16x2(t2, t3));
            }

#pragma unroll
            for (int j = 0; j < 8; j++) {
                o[j][0] *= f0; o[j][1] *= f0;
                o[j][2] *= f1; o[j][3] *= f1;
            }
            float dsum[4] = {0.f, 0.f, 0.f, 0.f};

#pragma unroll
            for (int kt2 = 0; kt2 < 8; kt2++) {
                uint32_t ap[4] = { p[2 * kt2][0],     p[2 * kt2][1],
                                   p[2 * kt2 + 1][0], p[2 * kt2 + 1][1] };
                MMA_F16(dsum, ap, ones_frag);
#pragma unroll
                for (int nq = 0; nq < 4; nq++) {
                    const int row = (ch2 << 7) + (kt2 << 4) + (lane & 15);
                    const int cc  = (nq << 1) + (lane >> 4);
                    const uint32_t addr =
                        vb + (uint32_t)(row << 7) + ((cc ^ (row & 7)) << 4);
                    uint32_t t0, t1, t2, t3;
                    LDSM_X4_T(t0, t1, t2, t3, addr);
                    uint32_t b0[2] = {t0, t1}, b1[2] = {t2, t3};
                    MMA_F16(o[2 * nq],     ap, b0);
                    MMA_F16(o[2 * nq + 1], ap, b1);
                }
            }
            dn0 = dn0 * f0 + dsum[0];
            dn1 = dn1 * f1 + dsum[2];
            m0 = nm0; m1 = nm1;
        }

        const float i0 = 1.f / dn0, i1 = 1.f / dn1;
        const int tok_lo = b * W_ + q0 + r_lo;
        const int tok_hi = tok_lo + 8;
        const int colb   = (kv * G_ + g) * 64 + cpair;
#pragma unroll
        for (int nt = 0; nt < 8; nt++) {
            const uint32_t w0 = pack_h2(o[nt][0] * i0, o[nt][1] * i0);
            const uint32_t w1 = pack_h2(o[nt][2] * i1, o[nt][3] * i1);
            *reinterpret_cast<uint32_t*>(out + (size_t)tok_lo * ATTN_W + colb + nt * 8) = w0;
            *reinterpret_cast<uint32_t*>(out + (size_t)tok_hi * ATTN_W + colb + nt * 8) = w1;
        }
    }
}

// ---------------------------------------------------------------------------
// kernel_launch — single-stream schedule.
// ---------------------------------------------------------------------------
extern "C" void kernel_launch(void* const* d_in, const int* in_sizes, int n_in,
                              void* d_out, int out_size)
{
    const float* hs    = (const float*)d_in[0];
    const float* cosb  = (const float*)d_in[1];
    const float* sinb  = (const float*)d_in[2];
    const float* Wqkv  = (const float*)d_in[3];
    const float* bqkv  = (const float*)d_in[4];
    const float* Wo    = (const float*)d_in[5];
    const float* bo    = (const float*)d_in[6];
    const float* sinks = (const float*)d_in[7];
    float* out = (float*)d_out;

    __half* qkvh;  cudaGetSymbolAddress((void**)&qkvh,  g_qkv_h);
    __half* hsh;   cudaGetSymbolAddress((void**)&hsh,   g_hs_h);
    __half* wqkvh; cudaGetSymbolAddress((void**)&wqkvh, g_wqkv_h);
    __half* woh;   cudaGetSymbolAddress((void**)&woh,   g_wo_h);
    __half* attnh; cudaGetSymbolAddress((void**)&attnh, g_attn_h);

    cudaFuncSetAttribute(gemm_h<true>,
                         cudaFuncAttributeMaxDynamicSharedMemorySize, GM_SMEM);
    cudaFuncSetAttribute(gemm_h<false>,
                         cudaFuncAttributeMaxDynamicSharedMemorySize, GM_SMEM);
    cudaFuncSetAttribute(attn_tc,
                         cudaFuncAttributeMaxDynamicSharedMemorySize, AT_SMEM);

    // 0) prep: pure f2h (no transposes)
    prep_kernel<<<PREP_BLOCKS, 256>>>(hs, hsh, Wqkv, wqkvh, Wo, woh);

    // 1) QKV projection + bias + rope + q-scale, fp16 out
    gemm_h<true><<<dim3(QKV_OUT / 128, S_LEN / 128), 128, GM_SMEM>>>(
        hsh, wqkvh, bqkv, qkvh, cosb, sinb, QKV_OUT, HID_);

    // 2) tensor-core flash attention
    attn_tc<<<dim3(NB_, H_KV_), 256, AT_SMEM>>>(qkvh, sinks, attnh);

    // 3) output projection, fp32 out
    gemm_h<false><<<dim3((HID_ + 127) / 128, S_LEN / 128), 128, GM_SMEM>>>(
        attnh, woh, bo, out, nullptr, nullptr, HID_, ATTN_W);
}

// round 16
// speedup vs baseline: 1.0390x; 1.0390x over previous
#include <cuda_runtime.h>
#include <cuda_fp16.h>
#include <cstdint>

#define S_LEN   4096
#define HID_    2880
#define H_KV_   8
#define G_      8
#define W_      128
#define NB_     32
#define QKV_OUT 5120
#define ATTN_W  4096
#define HALF_   32

// ---------------------------------------------------------------------------
// Scratch
// ---------------------------------------------------------------------------
__device__ __half g_qkv_h  [(size_t)S_LEN * QKV_OUT];   // fp16 qkv (post-rope, q pre-scaled)
__device__ __half g_hs_h   [(size_t)S_LEN * HID_];
__device__ __half g_wqkvT_h[(size_t)QKV_OUT * HID_];
__device__ __half g_woT_h  [(size_t)HID_ * ATTN_W];
__device__ __half g_attn_h [(size_t)S_LEN * ATTN_W];

// ---------------------------------------------------------------------------
// PTX helpers (plain sm_100 ISA)
// ---------------------------------------------------------------------------
__device__ __forceinline__ uint32_t smem_u32(const void* p) {
    uint32_t a;
    asm("{ .reg .u64 t; cvta.to.shared.u64 t, %1; cvt.u32.u64 %0, t; }" : "=r"(a) : "l"(p));
    return a;
}
__device__ __forceinline__ void cpasync16(uint32_t dst, const void* src, uint32_t sz) {
    asm volatile("cp.async.cg.shared.global [%0], [%1], 16, %2;\n"
                 :: "r"(dst), "l"(src), "r"(sz) : "memory");
}
#define CP_COMMIT() asm volatile("cp.async.commit_group;" ::: "memory")
#define CP_WAIT1()  asm volatile("cp.async.wait_group 1;" ::: "memory")

#define LDSM_X4(d0, d1, d2, d3, a)                                             \
    asm volatile("ldmatrix.sync.aligned.m8n8.x4.shared.b16 {%0,%1,%2,%3}, [%4];"\
        : "=r"(d0), "=r"(d1), "=r"(d2), "=r"(d3) : "r"(a))

#define LDSM_X4_T(d0, d1, d2, d3, a)                                           \
    asm volatile("ldmatrix.sync.aligned.m8n8.x4.trans.shared.b16 {%0,%1,%2,%3}, [%4];"\
        : "=r"(d0), "=r"(d1), "=r"(d2), "=r"(d3) : "r"(a))

#define MMA_F16(d, a, b)                                                       \
    asm volatile("mma.sync.aligned.m16n8k16.row.col.f32.f16.f16.f32 "          \
        "{%0,%1,%2,%3}, {%4,%5,%6,%7}, {%8,%9}, {%0,%1,%2,%3};"                \
        : "+f"((d)[0]), "+f"((d)[1]), "+f"((d)[2]), "+f"((d)[3])               \
        : "r"((a)[0]), "r"((a)[1]), "r"((a)[2]), "r"((a)[3]),                  \
          "r"((b)[0]), "r"((b)[1]))

__device__ __forceinline__ uint32_t pack_h2(float x, float y) {
    __half2 h = __floats2half2_rn(x, y);
    return *reinterpret_cast<uint32_t*>(&h);
}
__device__ __forceinline__ uint32_t pack_f16x2(float lo, float hi) {
    uint32_t r;
    asm("cvt.rn.f16x2.f32 %0, %1, %2;" : "=r"(r) : "f"(hi), "f"(lo));
    return r;
}
__device__ __forceinline__ uint32_t ex2_h2(uint32_t x) {
    uint32_t r;
    asm("ex2.approx.f16x2 %0, %1;" : "=r"(r) : "r"(x));
    return r;
}

// ---------------------------------------------------------------------------
// fp16 GEMM (R11/R14 core): CTA 128x128, 4 warps, warp tile 64x64, K-step 64,
// 3-stage cp.async pipeline, double-buffered register fragments. B = Bt
// (N-major, K contiguous), straight ldmatrix.
// ---------------------------------------------------------------------------
#define GSTAGES     3
#define STAGE_BYTES 32768     // A 16KB + B 16KB
#define GM_SMEM     (GSTAGES * STAGE_BYTES)

template <bool ROPE>
__global__ void __launch_bounds__(128, 2)
gemm_h(const __half* __restrict__ A, const __half* __restrict__ Bt,
       const float* __restrict__ bias, void* __restrict__ Cv,
       const float* __restrict__ cosb, const float* __restrict__ sinb,
       int Nn, int K)
{
    extern __shared__ char smem[];
    const uint32_t sb = smem_u32(smem);
    const int tid  = threadIdx.x;
    const int wid  = tid >> 5;
    const int lane = tid & 31;
    const int m0   = blockIdx.y << 7;
    const int n0   = blockIdx.x << 7;
    const int wm   = (wid & 1) << 6;    // warp M offset: 0,64
    const int wn   = (wid >> 1) << 6;   // warp N offset: 0,64

    float acc[4][8][4];
#pragma unroll
    for (int a = 0; a < 4; a++)
#pragma unroll
        for (int b = 0; b < 8; b++)
#pragma unroll
            for (int c = 0; c < 4; c++) acc[a][b][c] = 0.f;

    const int nkt = K >> 6;

    auto load_stage = [&](int kt, int slot) {
        const uint32_t abase = sb + slot * STAGE_BYTES;
        const uint32_t bbase = abase + 16384;
        const int k0 = kt << 6;
#pragma unroll
        for (int j = 0; j < 8; j++) {
            const int f = tid + (j << 7);
            const int r = f >> 3, c = f & 7;
            const uint32_t off = (uint32_t)(r << 7) + ((c ^ (r & 7)) << 4);
            cpasync16(abase + off, A + (size_t)(m0 + r) * K + k0 + (c << 3), 16u);
        }
#pragma unroll
        for (int j = 0; j < 8; j++) {
            const int f = tid + (j << 7);
            const int r = f >> 3, c = f & 7;
            const uint32_t off = (uint32_t)(r << 7) + ((c ^ (r & 7)) << 4);
            const int nrow = n0 + r;
            const int srow = (nrow < Nn) ? nrow : 0;
            cpasync16(bbase + off, Bt + (size_t)srow * K + k0 + (c << 3),
                      (nrow < Nn) ? 16u : 0u);
        }
    };

    for (int s = 0; s < 2; s++) {
        if (s < nkt) load_stage(s, s);
        CP_COMMIT();
    }

    for (int t = 0; t < nkt; t++) {
        CP_WAIT1();
        __syncthreads();
        if (t + 2 < nkt) load_stage(t + 2, (t + 2) % 3);
        CP_COMMIT();

        const uint32_t abase = sb + (t % 3) * STAGE_BYTES;
        const uint32_t bbase = abase + 16384;

        auto ldfrags = [&](int kh, uint32_t (&af_b)[4][4], uint32_t (&bf_b)[8][2]) {
#pragma unroll
            for (int mt = 0; mt < 4; mt++) {
                const int r = wm + (mt << 4) + (lane & 15);
                const int c = (kh << 1) + (lane >> 4);
                const uint32_t addr =
                    abase + (uint32_t)(r << 7) + ((c ^ (r & 7)) << 4);
                LDSM_X4(af_b[mt][0], af_b[mt][1], af_b[mt][2], af_b[mt][3], addr);
            }
#pragma unroll
            for (int nq = 0; nq < 4; nq++) {
                const int r = wn + (nq << 4) + ((lane >> 4) << 3) + (lane & 7);
                const int c = (kh << 1) + ((lane >> 3) & 1);
                const uint32_t addr =
                    bbase + (uint32_t)(r << 7) + ((c ^ (r & 7)) << 4);
                uint32_t t0, t1, t2, t3;
                LDSM_X4(t0, t1, t2, t3, addr);
                bf_b[nq * 2][0] = t0;     bf_b[nq * 2][1] = t1;
                bf_b[nq * 2 + 1][0] = t2; bf_b[nq * 2 + 1][1] = t3;
            }
        };

        uint32_t af[2][4][4];
        uint32_t bf[2][8][2];
        ldfrags(0, af[0], bf[0]);

#pragma unroll
        for (int kh = 0; kh < 4; kh++) {
            const int cur = kh & 1;
            if (kh < 3) ldfrags(kh + 1, af[cur ^ 1], bf[cur ^ 1]);
#pragma unroll
            for (int mt = 0; mt < 4; mt++)
#pragma unroll
                for (int nt = 0; nt < 8; nt++)
                    MMA_F16(acc[mt][nt], af[cur][mt], bf[cur][nt]);
        }
    }

    // ---- epilogue ----
    const int r_l = lane >> 2;
    const int c_l = (lane & 3) << 1;

#pragma unroll
    for (int mt = 0; mt < 4; mt++)
#pragma unroll
        for (int nt = 0; nt < 8; nt++) {
            const int col = n0 + wn + (nt << 3) + c_l;
            if (col < Nn) {
                const float2 bz = *reinterpret_cast<const float2*>(bias + col);
                acc[mt][nt][0] += bz.x; acc[mt][nt][1] += bz.y;
                acc[mt][nt][2] += bz.x; acc[mt][nt][3] += bz.y;
            }
        }

    if (ROPE) {
        const int hidx = (n0 + wn) >> 6;       // head index (warp N-tile head-aligned)
        if (hidx < 72) {                        // q + k heads get rope
#pragma unroll
            for (int mt = 0; mt < 4; mt++) {
                const int r0 = m0 + wm + (mt << 4) + r_l;
#pragma unroll
                for (int nt = 0; nt < 4; nt++) {
                    const int d = (nt << 3) + c_l;          // 0..30 (pair with d+32)
                    const float2 c0 = *reinterpret_cast<const float2*>(cosb + (size_t)r0 * 32 + d);
                    const float2 s0 = *reinterpret_cast<const float2*>(sinb + (size_t)r0 * 32 + d);
                    const float2 c1 = *reinterpret_cast<const float2*>(cosb + (size_t)(r0 + 8) * 32 + d);
                    const float2 s1 = *reinterpret_cast<const float2*>(sinb + (size_t)(r0 + 8) * 32 + d);
                    float x1, x2;
                    x1 = acc[mt][nt][0]; x2 = acc[mt][nt + 4][0];
                    acc[mt][nt][0]     = x1 * c0.x - x2 * s0.x;
                    acc[mt][nt + 4][0] = x2 * c0.x + x1 * s0.x;
                    x1 = acc[mt][nt][1]; x2 = acc[mt][nt + 4][1];
                    acc[mt][nt][1]     = x1 * c0.y - x2 * s0.y;
                    acc[mt][nt + 4][1] = x2 * c0.y + x1 * s0.y;
                    x1 = acc[mt][nt][2]; x2 = acc[mt][nt + 4][2];
                    acc[mt][nt][2]     = x1 * c1.x - x2 * s1.x;
                    acc[mt][nt + 4][2] = x2 * c1.x + x1 * s1.x;
                    x1 = acc[mt][nt][3]; x2 = acc[mt][nt + 4][3];
                    acc[mt][nt][3]     = x1 * c1.y - x2 * s1.y;
                    acc[mt][nt + 4][3] = x2 * c1.y + x1 * s1.y;
                }
            }
        }
        if (hidx < 64) {                        // fold 1/sqrt(d) into q
#pragma unroll
            for (int mt = 0; mt < 4; mt++)
#pragma unroll
                for (int nt = 0; nt < 8; nt++) {
                    acc[mt][nt][0] *= 0.125f; acc[mt][nt][1] *= 0.125f;
                    acc[mt][nt][2] *= 0.125f; acc[mt][nt][3] *= 0.125f;
                }
        }
        __half* Ch = (__half*)Cv;
#pragma unroll
        for (int mt = 0; mt < 4; mt++) {
            const int row = m0 + wm + (mt << 4) + r_l;
#pragma unroll
            for (int nt = 0; nt < 8; nt++) {
                const int col = n0 + wn + (nt << 3) + c_l;
                *reinterpret_cast<uint32_t*>(Ch + (size_t)row * Nn + col) =
                    pack_h2(acc[mt][nt][0], acc[mt][nt][1]);
                *reinterpret_cast<uint32_t*>(Ch + (size_t)(row + 8) * Nn + col) =
                    pack_h2(acc[mt][nt][2], acc[mt][nt][3]);
            }
        }
    } else {
        float* C = (float*)Cv;
#pragma unroll
        for (int mt = 0; mt < 4; mt++) {
            const int row = m0 + wm + (mt << 4) + r_l;
#pragma unroll
            for (int nt = 0; nt < 8; nt++) {
                const int col = n0 + wn + (nt << 3) + c_l;
                if (col < Nn) {
                    float2 o0, o1;
                    o0.x = acc[mt][nt][0]; o0.y = acc[mt][nt][1];
                    o1.x = acc[mt][nt][2]; o1.y = acc[mt][nt][3];
                    *reinterpret_cast<float2*>(C + (size_t)row * Nn + col)       = o0;
                    *reinterpret_cast<float2*>(C + (size_t)(row + 8) * Nn + col) = o1;
                }
            }
        }
    }
}

// ---------------------------------------------------------------------------
// Unified prep kernel: f2h(hidden) + transpose(Wqkv) + transpose(Wo).
// R16 transpose: float4 coalesced loads, uint2 (4-half) stores,
// conflict-free smem banks in both phases.
// ---------------------------------------------------------------------------
#define PREP_F2H_BLOCKS 11520            // 4096*2880/4/256
#define PREP_T1_BLOCKS  14400            // (5120/32)*(2880/32)
#define PREP_T2_BLOCKS  11520            // (2880/32)*(4096/32)
#define PREP_BLOCKS     (PREP_F2H_BLOCKS + PREP_T1_BLOCKS + PREP_T2_BLOCKS)

__global__ void __launch_bounds__(256)
prep_kernel(const float* __restrict__ hs,   __half* __restrict__ hsh,
            const float* __restrict__ Wqkv, __half* __restrict__ wqkvT,
            const float* __restrict__ Wo,   __half* __restrict__ woT)
{
    const int bid = blockIdx.x;
    const int tid = threadIdx.x;

    if (bid < PREP_F2H_BLOCKS) {                       // fp32 -> fp16 copy
        const int i = bid * 256 + tid;
        const float4 v = reinterpret_cast<const float4*>(hs)[i];
        __half2* d = reinterpret_cast<__half2*>(hsh) + 2 * i;
        d[0] = __floats2half2_rn(v.x, v.y);
        d[1] = __floats2half2_rn(v.z, v.w);
        return;
    }

    __shared__ float t[32][33];
    const float* src; __half* dst; int R, Cc, bx, by;
    if (bid < PREP_F2H_BLOCKS + PREP_T1_BLOCKS) {
        const int tb = bid - PREP_F2H_BLOCKS;
        src = Wqkv; dst = wqkvT; R = HID_; Cc = QKV_OUT;
        bx = (tb % 160) << 5; by = (tb / 160) << 5;
    } else {
        const int tb = bid - (PREP_F2H_BLOCKS + PREP_T1_BLOCKS);
        src = Wo; dst = woT; R = ATTN_W; Cc = HID_;
        bx = (tb % 90) << 5; by = (tb / 90) << 5;
    }
    // load phase: 256 threads x one float4 = 32 rows x 32 cols
    {
        const int ty = tid >> 3;          // src row 0..31
        const int tx = tid & 7;           // float4 column group 0..7
        const float4 v = *reinterpret_cast<const float4*>(
            src + (size_t)(by + ty) * Cc + bx + (tx << 2));
        t[ty][(tx << 2) + 0] = v.x;
        t[ty][(tx << 2) + 1] = v.y;
        t[ty][(tx << 2) + 2] = v.z;
        t[ty][(tx << 2) + 3] = v.w;
    }
    __syncthreads();
    // store phase: thread (r=ty, tx) writes dst[bx+r][by + tx*4 .. +3]
    {
        const int r  = tid >> 3;          // dst row (= src col) 0..31
        const int tx = tid & 7;
        const int c0 = tx << 2;           // src-row group
        uint2 o;
        o.x = pack_h2(t[r][0] * 0.f + t[c0 + 0][r], t[c0 + 1][r]);  // placeholder avoided below
        // (compute cleanly:)
        o.x = pack_h2(t[c0 + 0][r], t[c0 + 1][r]);
        o.y = pack_h2(t[c0 + 2][r], t[c0 + 3][r]);
        *reinterpret_cast<uint2*>(dst + (size_t)(bx + r) * R + by + c0) = o;
    }
}

// ---------------------------------------------------------------------------
// Tensor-core sliding-window flash attention with sinks (R14 version:
// fp16x2 ex2 softmax, denominators via P @ ones MMA).
// ---------------------------------------------------------------------------
#define AT_SMEM 81920   // K 32KB | V 32KB | Q 16KB

__global__ void __launch_bounds__(256, 1)
attn_tc(const __half* __restrict__ qkv, const float* __restrict__ sinks,
        __half* __restrict__ out)
{
    extern __shared__ __align__(16) char asmem[];
    char* Kc = asmem;
    char* Vc = asmem + 32768;
    char* Qc = asmem + 65536;
    const uint32_t kb = smem_u32(Kc);
    const uint32_t vb = smem_u32(Vc);
    const uint32_t qb = smem_u32(Qc);

    const int b    = blockIdx.x;
    const int kv   = blockIdx.y;
    const int tid  = threadIdx.x;
    const int wid  = tid >> 5;
    const int lane = tid & 31;

    for (int i = tid; i < 2048; i += 256) {
        const int tk = i >> 3, c = i & 7;
        uint4 kk = make_uint4(0u, 0u, 0u, 0u), vv = kk;
        if (tk >= 128 || b > 0) {
            const int token = (tk < 128) ? ((b - 1) * W_ + tk) : (b * W_ + tk - 128);
            const __half* kp = qkv + (size_t)token * QKV_OUT + 4096 + kv * 64 + c * 8;
            kk = *reinterpret_cast<const uint4*>(kp);
            vv = *reinterpret_cast<const uint4*>(kp + 512);
        }
        const uint32_t off = (uint32_t)(tk << 7) + ((c ^ (tk & 7)) << 4);
        *reinterpret_cast<uint4*>(Kc + off) = kk;
        *reinterpret_cast<uint4*>(Vc + off) = vv;
    }

    const int q0    = wid << 4;
    const int r_lo  = lane >> 2;
    const int cpair = (lane & 3) << 1;
    const uint32_t ONES2 = 0x3C003C00u;
    const uint32_t ones_frag[2] = { ONES2, ONES2 };
    const float L2E = 1.4426950408889634f;

    for (int g = 0; g < G_; g++) {
        __syncthreads();
        for (int i = tid; i < 1024; i += 256) {
            const int r = i >> 3, c = i & 7;
            const __half* qp = qkv + (size_t)(b * W_ + r) * QKV_OUT
                               + (kv * G_ + g) * 64 + c * 8;
            *reinterpret_cast<uint4*>(Qc + (r << 7) + ((c ^ (r & 7)) << 4)) =
                *reinterpret_cast<const uint4*>(qp);
        }
        __syncthreads();

        uint32_t aq[4][4];
#pragma unroll
        for (int kt = 0; kt < 4; kt++) {
            const int row = q0 + (lane & 15);
            const int ch  = (kt << 1) + (lane >> 4);
            const uint32_t addr = qb + (uint32_t)(row << 7) + ((ch ^ (row & 7)) << 4);
            LDSM_X4(aq[kt][0], aq[kt][1], aq[kt][2], aq[kt][3], addr);
        }

        const float sink = sinks[kv * G_ + g];
        float m0 = sink, m1 = sink;
        float dn0 = 1.f, dn1 = 1.f;
        float o[8][4];
#pragma unroll
        for (int j = 0; j < 8; j++)
#pragma unroll
            for (int c = 0; c < 4; c++) o[j][c] = 0.f;

#pragma unroll
        for (int ch2 = 0; ch2 < 2; ch2++) {
            if (b == 0 && ch2 == 0) continue;

            float s[16][4];
#pragma unroll
            for (int nt = 0; nt < 16; nt++)
#pragma unroll
                for (int c = 0; c < 4; c++) s[nt][c] = 0.f;

#pragma unroll
            for (int nt2 = 0; nt2 < 8; nt2++) {
#pragma unroll
                for (int kt = 0; kt < 4; kt++) {
                    const int row = (ch2 << 7) + (nt2 << 4)
                                    + ((lane >> 4) << 3) + (lane & 7);
                    const int cc  = (kt << 1) + ((lane >> 3) & 1);
                    const uint32_t addr =
                        kb + (uint32_t)(row << 7) + ((cc ^ (row & 7)) << 4);
                    uint32_t t0, t1, t2, t3;
                    LDSM_X4(t0, t1, t2, t3, addr);
                    uint32_t bf0[2] = {t0, t1}, bf1[2] = {t2, t3};
                    MMA_F16(s[nt2 * 2],     aq[kt], bf0);
                    MMA_F16(s[nt2 * 2 + 1], aq[kt], bf1);
                }
            }

            const int qi_lo = q0 + r_lo;
            const int qi_hi = qi_lo + 8;
#pragma unroll
            for (int nt = 0; nt < 16; nt++) {
                const int ki = (ch2 << 7) + (nt << 3) + cpair;
                const int d0i = ki - qi_lo, d1i = ki + 1 - qi_lo;
                const int d2i = ki - qi_hi, d3i = ki + 1 - qi_hi;
                if (d0i < 1 || d0i > 128) s[nt][0] = -1e30f;
                if (d1i < 1 || d1i > 128) s[nt][1] = -1e30f;
                if (d2i < 1 || d2i > 128) s[nt][2] = -1e30f;
                if (d3i < 1 || d3i > 128) s[nt][3] = -1e30f;
            }

            float mx0 = -1e30f, mx1 = -1e30f;
#pragma unroll
            for (int nt = 0; nt < 16; nt++) {
                mx0 = fmaxf(mx0, fmaxf(s[nt][0], s[nt][1]));
                mx1 = fmaxf(mx1, fmaxf(s[nt][2], s[nt][3]));
            }
            mx0 = fmaxf(mx0, __shfl_xor_sync(0xffffffffu, mx0, 1));
            mx0 = fmaxf(mx0, __shfl_xor_sync(0xffffffffu, mx0, 2));
            mx1 = fmaxf(mx1, __shfl_xor_sync(0xffffffffu, mx1, 1));
            mx1 = fmaxf(mx1, __shfl_xor_sync(0xffffffffu, mx1, 2));
            const float nm0 = fmaxf(m0, mx0), nm1 = fmaxf(m1, mx1);
            const float f0 = __expf(m0 - nm0), f1 = __expf(m1 - nm1);

            const float c0a = -nm0 * L2E;
            const float c1a = -nm1 * L2E;
            uint32_t p[16][2];
#pragma unroll
            for (int nt = 0; nt < 16; nt++) {
                const float t0 = fmaf(s[nt][0], L2E, c0a);
                const float t1 = fmaf(s[nt][1], L2E, c0a);
                const float t2 = fmaf(s[nt][2], L2E, c1a);
                const float t3 = fmaf(s[nt][3], L2E, c1a);
                p[nt][0] = ex2_h2(pack_f16x2(t0, t1));
                p[nt][1] = ex2_h2(pack_f16x2(t2, t3));
            }

#pragma unroll
            for (int j = 0; j < 8; j++) {
                o[j][0] *= f0; o[j][1] *= f0;
                o[j][2] *= f1; o[j][3] *= f1;
            }
            float dsum[4] = {0.f, 0.f, 0.f, 0.f};

#pragma unroll
            for (int kt2 = 0; kt2 < 8; kt2++) {
                uint32_t ap[4] = { p[2 * kt2][0],     p[2 * kt2][1],
                                   p[2 * kt2 + 1][0], p[2 * kt2 + 1][1] };
                MMA_F16(dsum, ap, ones_frag);
#pragma unroll
                for (int nq = 0; nq < 4; nq++) {
                    const int row = (ch2 << 7) + (kt2 << 4) + (lane & 15);
                    const int cc  = (nq << 1) + (lane >> 4);
                    const uint32_t addr =
                        vb + (uint32_t)(row << 7) + ((cc ^ (row & 7)) << 4);
                    uint32_t t0, t1, t2, t3;
                    LDSM_X4_T(t0, t1, t2, t3, addr);
                    uint32_t b0[2] = {t0, t1}, b1[2] = {t2, t3};
                    MMA_F16(o[2 * nq],     ap, b0);
                    MMA_F16(o[2 * nq + 1], ap, b1);
                }
            }
            dn0 = dn0 * f0 + dsum[0];
            dn1 = dn1 * f1 + dsum[2];
            m0 = nm0; m1 = nm1;
        }

        const float i0 = 1.f / dn0, i1 = 1.f / dn1;
        const int tok_lo = b * W_ + q0 + r_lo;
        const int tok_hi = tok_lo + 8;
        const int colb   = (kv * G_ + g) * 64 + cpair;
#pragma unroll
        for (int nt = 0; nt < 8; nt++) {
            const uint32_t w0 = pack_h2(o[nt][0] * i0, o[nt][1] * i0);
            const uint32_t w1 = pack_h2(o[nt][2] * i1, o[nt][3] * i1);
            *reinterpret_cast<uint32_t*>(out + (size_t)tok_lo * ATTN_W + colb + nt * 8) = w0;
            *reinterpret_cast<uint32_t*>(out + (size_t)tok_hi * ATTN_W + colb + nt * 8) = w1;
        }
    }
}

// ---------------------------------------------------------------------------
// kernel_launch — single-stream R14 schedule.
// ---------------------------------------------------------------------------
extern "C" void kernel_launch(void* const* d_in, const int* in_sizes, int n_in,
                              void* d_out, int out_size)
{
    const float* hs    = (const float*)d_in[0];
    const float* cosb  = (const float*)d_in[1];
    const float* sinb  = (const float*)d_in[2];
    const float* Wqkv  = (const float*)d_in[3];
    const float* bqkv  = (const float*)d_in[4];
    const float* Wo    = (const float*)d_in[5];
    const float* bo    = (const float*)d_in[6];
    const float* sinks = (const float*)d_in[7];
    float* out = (float*)d_out;

    __half* qkvh;  cudaGetSymbolAddress((void**)&qkvh,  g_qkv_h);
    __half* hsh;   cudaGetSymbolAddress((void**)&hsh,   g_hs_h);
    __half* wqkvT; cudaGetSymbolAddress((void**)&wqkvT, g_wqkvT_h);
    __half* woT;   cudaGetSymbolAddress((void**)&woT,   g_woT_h);
    __half* attnh; cudaGetSymbolAddress((void**)&attnh, g_attn_h);

    cudaFuncSetAttribute(gemm_h<true>,
                         cudaFuncAttributeMaxDynamicSharedMemorySize, GM_SMEM);
    cudaFuncSetAttribute(gemm_h<false>,
                         cudaFuncAttributeMaxDynamicSharedMemorySize, GM_SMEM);
    cudaFuncSetAttribute(attn_tc,
                         cudaFuncAttributeMaxDynamicSharedMemorySize, AT_SMEM);

    // 0) unified operand prep (fp32->fp16 + 2 weight transposes, one launch)
    prep_kernel<<<PREP_BLOCKS, 256>>>(hs, hsh, Wqkv, wqkvT, Wo, woT);

    // 1) QKV projection + bias + rope + q-scale, fp16 out
    gemm_h<true><<<dim3(QKV_OUT / 128, S_LEN / 128), 128, GM_SMEM>>>(
        hsh, wqkvT, bqkv, qkvh, cosb, sinb, QKV_OUT, HID_);

    // 2) tensor-core flash attention
    attn_tc<<<dim3(NB_, H_KV_), 256, AT_SMEM>>>(qkvh, sinks, attnh);

    // 3) output projection, fp32 out
    gemm_h<false><<<dim3((HID_ + 127) / 128, S_LEN / 128), 128, GM_SMEM>>>(
        attnh, woT, bo, out, nullptr, nullptr, HID_, ATTN_W);
}